// round 15
// baseline (speedup 1.0000x reference)
#include <cuda_runtime.h>
#include <cuda_bf16.h>
#include <math.h>
#include <stdint.h>

// Problem constants
#define B_   8
#define S_   1024
#define D_   1024
#define H_   16
#define HD_  64
#define D3_  3072
#define KP_  3072              // split-bf16 K' = 3*1024
#define LDS_ 40                // smem row stride in bf16 (80B)

// GEMM smem layout (elements): A bufs then B bufs
#define ASZ  (128 * LDS_)
#define BSZ  (256 * LDS_)
#define GEMM_SMEM_BYTES ((2 * ASZ + 2 * BSZ) * 2)

// Scratch (device globals; no runtime allocation allowed)
__device__ __align__(128) float         g_qkv[(size_t)B_ * S_ * D3_]; // fp32 QKV
__device__ __align__(128) __nv_bfloat16 g_Aq[(size_t)B_ * S_ * KP_];  // query split
__device__ __align__(128) __nv_bfloat16 g_Ap[(size_t)B_ * S_ * KP_];  // attn-out split
__device__ __align__(128) __nv_bfloat16 g_Wq[(size_t)D3_ * KP_];      // w_qkv'  [N,K']
__device__ __align__(128) __nv_bfloat16 g_Wp[(size_t)D_  * KP_];      // w_proj' [N,K']

__device__ __forceinline__ uint32_t smem_u32(const void* p) {
    uint32_t a;
    asm("{ .reg .u64 t; cvta.to.shared.u64 t, %1; cvt.u32.u64 %0, t; }"
        : "=r"(a) : "l"(p));
    return a;
}

#define LDSM_X4(r0, r1, r2, r3, addr) \
    asm volatile("ldmatrix.sync.aligned.m8n8.x4.shared.b16 {%0,%1,%2,%3}, [%4];" \
                 : "=r"(r0), "=r"(r1), "=r"(r2), "=r"(r3) : "r"(addr))

#define MMA16816(c, a, b) \
    asm volatile("mma.sync.aligned.m16n8k16.row.col.f32.bf16.bf16.f32 " \
                 "{%0,%1,%2,%3}, {%4,%5,%6,%7}, {%8,%9}, {%0,%1,%2,%3};" \
                 : "+f"((c)[0]), "+f"((c)[1]), "+f"((c)[2]), "+f"((c)[3]) \
                 : "r"((a)[0]), "r"((a)[1]), "r"((a)[2]), "r"((a)[3]), \
                   "r"((b)[0]), "r"((b)[1]))

// pack two floats into bf16x2 hi + compensation lo registers
__device__ __forceinline__ void split2(float a, float b, uint32_t& hi, uint32_t& lo) {
    __nv_bfloat16 ha = __float2bfloat16(a), hb = __float2bfloat16(b);
    __nv_bfloat162 th; th.x = ha; th.y = hb;
    __nv_bfloat162 tl;
    tl.x = __float2bfloat16(a - __bfloat162float(ha));
    tl.y = __float2bfloat16(b - __bfloat162float(hb));
    hi = *reinterpret_cast<uint32_t*>(&th);
    lo = *reinterpret_cast<uint32_t*>(&tl);
}

// ---------------------------------------------------------------------------
// Prep: split fp32 activations [rows,1024] -> bf16 [rows,3072] = [hi | lo | hi]
// ---------------------------------------------------------------------------
__global__ __launch_bounds__(256) void conv_A_kernel(const float* __restrict__ in,
                                                     __nv_bfloat16* __restrict__ out) {
    int idx = blockIdx.x * 256 + threadIdx.x;          // one float4 each
    int r = idx >> 8, c4 = (idx & 255) * 4;
    float4 v = *(const float4*)(in + (size_t)r * 1024 + c4);
    float f[4] = {v.x, v.y, v.z, v.w};
    __nv_bfloat16 h[4], l[4];
#pragma unroll
    for (int j = 0; j < 4; j++) {
        h[j] = __float2bfloat16(f[j]);
        l[j] = __float2bfloat16(f[j] - __bfloat162float(h[j]));
    }
    __nv_bfloat16* o = out + (size_t)r * KP_;
    __nv_bfloat162 hp0, hp1, lp0, lp1;
    hp0.x = h[0]; hp0.y = h[1]; hp1.x = h[2]; hp1.y = h[3];
    lp0.x = l[0]; lp0.y = l[1]; lp1.x = l[2]; lp1.y = l[3];
    *(__nv_bfloat162*)(o + c4)        = hp0; *(__nv_bfloat162*)(o + c4 + 2)        = hp1;
    *(__nv_bfloat162*)(o + 1024 + c4) = lp0; *(__nv_bfloat162*)(o + 1024 + c4 + 2) = lp1;
    *(__nv_bfloat162*)(o + 2048 + c4) = hp0; *(__nv_bfloat162*)(o + 2048 + c4 + 2) = hp1;
}

// ---------------------------------------------------------------------------
// Prep: transpose+split weights W[1024,N] fp32 -> W'[N,3072] bf16 = [hi | hi | lo]
// ---------------------------------------------------------------------------
__global__ __launch_bounds__(256) void conv_W_kernel(const float* __restrict__ W,
                                                     __nv_bfloat16* __restrict__ out, int N) {
    __shared__ float t[32][33];
    int n0 = blockIdx.x * 32, k0 = blockIdx.y * 32;
    int tx = threadIdx.x & 31, ty = threadIdx.x >> 5;
#pragma unroll
    for (int i = 0; i < 4; i++)
        t[ty + i * 8][tx] = W[(size_t)(k0 + ty + i * 8) * N + n0 + tx];
    __syncthreads();
    int ny = threadIdx.x >> 3, kq = (threadIdx.x & 7) * 4;
    __nv_bfloat16 h[4], l[4];
#pragma unroll
    for (int j = 0; j < 4; j++) {
        float x = t[kq + j][ny];
        h[j] = __float2bfloat16(x);
        l[j] = __float2bfloat16(x - __bfloat162float(h[j]));
    }
    __nv_bfloat16* o = out + (size_t)(n0 + ny) * KP_ + k0 + kq;
    __nv_bfloat162 hp0, hp1, lp0, lp1;
    hp0.x = h[0]; hp0.y = h[1]; hp1.x = h[2]; hp1.y = h[3];
    lp0.x = l[0]; lp0.y = l[1]; lp1.x = l[2]; lp1.y = l[3];
    *(__nv_bfloat162*)(o)        = hp0; *(__nv_bfloat162*)(o + 2)        = hp1;
    *(__nv_bfloat162*)(o + 1024) = hp0; *(__nv_bfloat162*)(o + 1024 + 2) = hp1;
    *(__nv_bfloat162*)(o + 2048) = lp0; *(__nv_bfloat162*)(o + 2048 + 2) = lp1;
}

// ---------------------------------------------------------------------------
// mma.sync GEMM: C[M,N] = A'[M,K'] @ W'[N,K']^T + bias  (bf16 in, fp32 accum)
// CTA tile 128x256, 8 warps (2x4), warp tile 64x64, BK=32, double-buffered
// dynamic smem (60KB). Widened from 64x32 to cut L1 traffic per MMA ~1.45x
// (R12 profile: L1=85.7% binding, tensor=46.7%).
// ---------------------------------------------------------------------------
__global__ __launch_bounds__(256) void mma_gemm_kernel(
    const __nv_bfloat16* __restrict__ A, const __nv_bfloat16* __restrict__ W,
    const float* __restrict__ bias, float* __restrict__ C, int N)
{
    extern __shared__ __align__(16) __nv_bfloat16 dsm[];
    // element offsets: A buf b at b*ASZ ; B buf b at 2*ASZ + b*BSZ

    const int tid = threadIdx.x, wid = tid >> 5, lane = tid & 31;
    const int wm = wid >> 2, wn = wid & 3;             // warp grid 2(m) x 4(n)
    const int m0 = blockIdx.y * 128, n0 = blockIdx.x * 256;

    // loaders: lin -> (row, 8-col chunk); A: 512 uint4, B: 1024 uint4
    const int lr = tid >> 2;                           // 0..63 base row
    const int lc = (tid & 3) * 8;                      // bf16 col offset in BK=32

    float acc[4][8][4];
#pragma unroll
    for (int i = 0; i < 4; i++)
#pragma unroll
        for (int j = 0; j < 8; j++)
#pragma unroll
            for (int k = 0; k < 4; k++) acc[i][j][k] = 0.f;

    // prologue: tile 0 -> buffer 0
#pragma unroll
    for (int i = 0; i < 2; i++) {
        int r = lr + i * 64;
        *(uint4*)&dsm[0 * ASZ + r * LDS_ + lc] =
            *(const uint4*)(A + (size_t)(m0 + r) * KP_ + lc);
    }
#pragma unroll
    for (int i = 0; i < 4; i++) {
        int r = lr + i * 64;
        *(uint4*)&dsm[2 * ASZ + r * LDS_ + lc] =
            *(const uint4*)(W + (size_t)(n0 + r) * KP_ + lc);
    }
    __syncthreads();

    const uint32_t smb = smem_u32(dsm);
    // A-fragment addressing (identical contract to validated 64x32 kernel)
    const uint32_t a_row = wm * 64 + (lane & 15);
    const uint32_t a_kof = (lane >> 4) * 8;
    // B-fragment addressing, warp covers 64 n-cols
    const uint32_t b_row = wn * 64 + (lane & 7) + ((lane >> 4) & 1) * 8;
    const uint32_t b_kof = ((lane >> 3) & 1) * 8;

    int buf = 0;
    for (int kt = 0; kt < KP_; kt += 32) {
        const bool more = (kt + 32) < KP_;
        uint4 pa[2], pb[4];
        if (more) {
#pragma unroll
            for (int i = 0; i < 2; i++)
                pa[i] = *(const uint4*)(A + (size_t)(m0 + lr + i * 64) * KP_ + kt + 32 + lc);
#pragma unroll
            for (int i = 0; i < 4; i++)
                pb[i] = *(const uint4*)(W + (size_t)(n0 + lr + i * 64) * KP_ + kt + 32 + lc);
        }

        const uint32_t abase = smb + (uint32_t)(buf * ASZ) * 2;
        const uint32_t bbase = smb + (uint32_t)(2 * ASZ + buf * BSZ) * 2;
#pragma unroll
        for (int ks = 0; ks < 2; ks++) {               // two k16 sub-steps
            uint32_t a[4][4], b[8][2];
#pragma unroll
            for (int mi = 0; mi < 4; mi++) {
                uint32_t ad = abase + (((a_row + mi * 16) * LDS_) + ks * 16 + a_kof) * 2;
                LDSM_X4(a[mi][0], a[mi][1], a[mi][2], a[mi][3], ad);
            }
#pragma unroll
            for (int nj = 0; nj < 4; nj++) {           // 8 n8-frags via 4 x4 loads
                uint32_t bd = bbase + (((b_row + nj * 16) * LDS_) + ks * 16 + b_kof) * 2;
                LDSM_X4(b[2 * nj][0], b[2 * nj][1], b[2 * nj + 1][0], b[2 * nj + 1][1], bd);
            }
#pragma unroll
            for (int mi = 0; mi < 4; mi++)
#pragma unroll
                for (int ni = 0; ni < 8; ni++)
                    MMA16816(acc[mi][ni], a[mi], b[ni]);
        }

        if (more) {
            const int nb = buf ^ 1;
#pragma unroll
            for (int i = 0; i < 2; i++)
                *(uint4*)&dsm[nb * ASZ + (lr + i * 64) * LDS_ + lc] = pa[i];
#pragma unroll
            for (int i = 0; i < 4; i++)
                *(uint4*)&dsm[2 * ASZ + nb * BSZ + (lr + i * 64) * LDS_ + lc] = pb[i];
        }
        __syncthreads();
        buf ^= 1;
    }

    // epilogue: c frag rows t/4, t/4+8; cols 2*(t%4)+{0,1}
    const int erow = m0 + wm * 64 + (lane >> 2);
    const int ecol = n0 + wn * 64 + (lane & 3) * 2;
#pragma unroll
    for (int mi = 0; mi < 4; mi++) {
#pragma unroll
        for (int ni = 0; ni < 8; ni++) {
            int r0 = erow + mi * 16, c0 = ecol + ni * 8;
            float b0 = bias[c0], b1 = bias[c0 + 1];
            float2 v0 = make_float2(acc[mi][ni][0] + b0, acc[mi][ni][1] + b1);
            float2 v1 = make_float2(acc[mi][ni][2] + b0, acc[mi][ni][3] + b1);
            *(float2*)&C[(size_t)r0 * N + c0]       = v0;
            *(float2*)&C[(size_t)(r0 + 8) * N + c0] = v1;
        }
    }
}

// ---------------------------------------------------------------------------
// Tensor-core flash attention: g_qkv -> g_Ap (split-bf16 [hi|lo|hi] output)
// (byte-identical to the R12-validated kernel)
// ---------------------------------------------------------------------------
__global__ __launch_bounds__(256) void flash_mma_kernel()
{
    __shared__ __align__(16) __nv_bfloat16 sm[18432];   // 36 KB
    const int STR = 72;
    const int QHI = 0, QLO = 9216;
    const int KHI = 0, KLO = 4608, VTHI = 9216, VTLO = 13824;

    const int bz = blockIdx.z, h = blockIdx.y, q0 = blockIdx.x * 128;
    const int tid = threadIdx.x, wid = tid >> 5, lane = tid & 31;
    const float* base = g_qkv + (size_t)bz * S_ * D3_ + h * HD_;

    {
        int qr = tid >> 1, db = (tid & 1) * 32;
        const float* qp = base + (size_t)(q0 + qr) * D3_ + db;
#pragma unroll
        for (int i = 0; i < 8; i++) {
            float4 v = *(const float4*)(qp + i * 4);
            uint32_t hi, lo;
            split2(v.x * 0.125f, v.y * 0.125f, hi, lo);
            *(uint32_t*)&sm[QHI + qr * STR + db + i * 4]     = hi;
            *(uint32_t*)&sm[QLO + qr * STR + db + i * 4]     = lo;
            split2(v.z * 0.125f, v.w * 0.125f, hi, lo);
            *(uint32_t*)&sm[QHI + qr * STR + db + i * 4 + 2] = hi;
            *(uint32_t*)&sm[QLO + qr * STR + db + i * 4 + 2] = lo;
        }
    }
    __syncthreads();

    const uint32_t smb = smem_u32(sm);
    const int arow = wid * 16 + (lane & 15);
    const int akof = (lane >> 4) * 8;
    uint32_t qh[4][4], ql[4][4];
#pragma unroll
    for (int s = 0; s < 4; s++) {
        LDSM_X4(qh[s][0], qh[s][1], qh[s][2], qh[s][3],
                smb + (uint32_t)(QHI + arow * STR + s * 16 + akof) * 2);
        LDSM_X4(ql[s][0], ql[s][1], ql[s][2], ql[s][3],
                smb + (uint32_t)(QLO + arow * STR + s * 16 + akof) * 2);
    }
    __syncthreads();

    float o[8][4];
#pragma unroll
    for (int j = 0; j < 8; j++)
#pragma unroll
        for (int k = 0; k < 4; k++) o[j][k] = 0.f;
    float m0 = -INFINITY, m1 = -INFINITY, l0 = 0.f, l1 = 0.f;

    const int brow = (lane & 7) + ((lane >> 4) & 1) * 8;
    const int bkof = ((lane >> 3) & 1) * 8;

    for (int kt = 0; kt < S_; kt += 64) {
        {
            int key = tid >> 2, db = (tid & 3) * 16;
            const float* kp = base + (size_t)(kt + key) * D3_ + 1024 + db;
#pragma unroll
            for (int i = 0; i < 4; i++) {
                float4 v = *(const float4*)(kp + i * 4);
                uint32_t hi, lo;
                split2(v.x, v.y, hi, lo);
                *(uint32_t*)&sm[KHI + key * STR + db + i * 4]     = hi;
                *(uint32_t*)&sm[KLO + key * STR + db + i * 4]     = lo;
                split2(v.z, v.w, hi, lo);
                *(uint32_t*)&sm[KHI + key * STR + db + i * 4 + 2] = hi;
                *(uint32_t*)&sm[KLO + key * STR + db + i * 4 + 2] = lo;
            }
            const float* vp = base + (size_t)(kt + key) * D3_ + 2048;
            int c = tid & 3;
#pragma unroll
            for (int i = 0; i < 16; i++) {
                int d = c + 4 * i;
                float v = vp[d];
                __nv_bfloat16 hh = __float2bfloat16(v);
                sm[VTHI + d * STR + key] = hh;
                sm[VTLO + d * STR + key] = __float2bfloat16(v - __bfloat162float(hh));
            }
        }
        __syncthreads();

        float sf[8][4];
#pragma unroll
        for (int j = 0; j < 8; j++)
#pragma unroll
            for (int k = 0; k < 4; k++) sf[j][k] = 0.f;
#pragma unroll
        for (int s = 0; s < 4; s++) {
            uint32_t bh[8][2], bl[8][2];
#pragma unroll
            for (int nj = 0; nj < 4; nj++) {
                uint32_t ad = smb + (uint32_t)(KHI + (brow + 16 * nj) * STR + s * 16 + bkof) * 2;
                LDSM_X4(bh[2 * nj][0], bh[2 * nj][1], bh[2 * nj + 1][0], bh[2 * nj + 1][1], ad);
                uint32_t al = smb + (uint32_t)(KLO + (brow + 16 * nj) * STR + s * 16 + bkof) * 2;
                LDSM_X4(bl[2 * nj][0], bl[2 * nj][1], bl[2 * nj + 1][0], bl[2 * nj + 1][1], al);
            }
#pragma unroll
            for (int j = 0; j < 8; j++) {
                MMA16816(sf[j], qh[s], bh[j]);
                MMA16816(sf[j], ql[s], bh[j]);
                MMA16816(sf[j], qh[s], bl[j]);
            }
        }

        float mx0 = -INFINITY, mx1 = -INFINITY;
#pragma unroll
        for (int j = 0; j < 8; j++) {
            mx0 = fmaxf(mx0, fmaxf(sf[j][0], sf[j][1]));
            mx1 = fmaxf(mx1, fmaxf(sf[j][2], sf[j][3]));
        }
#pragma unroll
        for (int off = 1; off <= 2; off <<= 1) {
            mx0 = fmaxf(mx0, __shfl_xor_sync(0xffffffffu, mx0, off));
            mx1 = fmaxf(mx1, __shfl_xor_sync(0xffffffffu, mx1, off));
        }
        float mn0 = fmaxf(m0, mx0), mn1 = fmaxf(m1, mx1);
        float f0 = __expf(m0 - mn0), f1 = __expf(m1 - mn1);
        m0 = mn0; m1 = mn1;

        float rs0 = 0.f, rs1 = 0.f;
        uint32_t pH0[8], pH1[8], pL0[8], pL1[8];
#pragma unroll
        for (int j = 0; j < 8; j++) {
            float p0 = __expf(sf[j][0] - mn0), p1 = __expf(sf[j][1] - mn0);
            float p2 = __expf(sf[j][2] - mn1), p3 = __expf(sf[j][3] - mn1);
            rs0 += p0 + p1; rs1 += p2 + p3;
            split2(p0, p1, pH0[j], pL0[j]);
            split2(p2, p3, pH1[j], pL1[j]);
        }
#pragma unroll
        for (int off = 1; off <= 2; off <<= 1) {
            rs0 += __shfl_xor_sync(0xffffffffu, rs0, off);
            rs1 += __shfl_xor_sync(0xffffffffu, rs1, off);
        }
        l0 = l0 * f0 + rs0;
        l1 = l1 * f1 + rs1;
#pragma unroll
        for (int j = 0; j < 8; j++) {
            o[j][0] *= f0; o[j][1] *= f0; o[j][2] *= f1; o[j][3] *= f1;
        }

#pragma unroll
        for (int t = 0; t < 4; t++) {
            uint32_t vh[8][2], vl[8][2];
#pragma unroll
            for (int nj = 0; nj < 4; nj++) {
                uint32_t ad = smb + (uint32_t)(VTHI + (brow + 16 * nj) * STR + t * 16 + bkof) * 2;
                LDSM_X4(vh[2 * nj][0], vh[2 * nj][1], vh[2 * nj + 1][0], vh[2 * nj + 1][1], ad);
                uint32_t al = smb + (uint32_t)(VTLO + (brow + 16 * nj) * STR + t * 16 + bkof) * 2;
                LDSM_X4(vl[2 * nj][0], vl[2 * nj][1], vl[2 * nj + 1][0], vl[2 * nj + 1][1], al);
            }
            uint32_t aH[4] = {pH0[2 * t], pH1[2 * t], pH0[2 * t + 1], pH1[2 * t + 1]};
            uint32_t aL[4] = {pL0[2 * t], pL1[2 * t], pL0[2 * t + 1], pL1[2 * t + 1]};
#pragma unroll
            for (int jd = 0; jd < 8; jd++) {
                MMA16816(o[jd], aH, vh[jd]);
                MMA16816(o[jd], aL, vh[jd]);
                MMA16816(o[jd], aH, vl[jd]);
            }
        }
        __syncthreads();
    }

    const float inv0 = 1.f / l0, inv1 = 1.f / l1;
    const size_t row0 = (size_t)bz * S_ + q0 + wid * 16 + (lane >> 2);
    __nv_bfloat16* op0 = g_Ap + row0 * KP_ + h * HD_ + 2 * (lane & 3);
    __nv_bfloat16* op1 = op0 + (size_t)8 * KP_;
#pragma unroll
    for (int jd = 0; jd < 8; jd++) {
        uint32_t hi, lo;
        split2(o[jd][0] * inv0, o[jd][1] * inv0, hi, lo);
        *(uint32_t*)(op0 + 8 * jd)        = hi;
        *(uint32_t*)(op0 + 8 * jd + 1024) = lo;
        *(uint32_t*)(op0 + 8 * jd + 2048) = hi;
        split2(o[jd][2] * inv1, o[jd][3] * inv1, hi, lo);
        *(uint32_t*)(op1 + 8 * jd)        = hi;
        *(uint32_t*)(op1 + 8 * jd + 1024) = lo;
        *(uint32_t*)(op1 + 8 * jd + 2048) = hi;
    }
}

// ---------------------------------------------------------------------------
extern "C" void kernel_launch(void* const* d_in, const int* in_sizes, int n_in,
                              void* d_out, int out_size)
{
    const float* query  = (const float*)d_in[0];
    const float* w_qkv  = (const float*)d_in[1];
    const float* b_qkv  = (const float*)d_in[2];
    const float* w_proj = (const float*)d_in[3];
    const float* b_proj = (const float*)d_in[4];
    float* out = (float*)d_out;

    float* qkv = nullptr;
    __nv_bfloat16 *Aq = nullptr, *Ap = nullptr, *Wq = nullptr, *Wp = nullptr;
    cudaGetSymbolAddress((void**)&qkv, g_qkv);
    cudaGetSymbolAddress((void**)&Aq, g_Aq);
    cudaGetSymbolAddress((void**)&Ap, g_Ap);
    cudaGetSymbolAddress((void**)&Wq, g_Wq);
    cudaGetSymbolAddress((void**)&Wp, g_Wp);

    cudaFuncSetAttribute(mma_gemm_kernel,
                         cudaFuncAttributeMaxDynamicSharedMemorySize, GEMM_SMEM_BYTES);

    // prep: split/transpose
    conv_A_kernel<<<(B_ * S_ * 1024) / (256 * 4), 256>>>(query, Aq);
    conv_W_kernel<<<dim3(D3_ / 32, 32), 256>>>(w_qkv, Wq, D3_);
    conv_W_kernel<<<dim3(D_ / 32, 32), 256>>>(w_proj, Wp, D_);

    // 1) QKV projection (HMMA): [8192,3072'] @ [3072,3072']^T -> fp32 g_qkv
    mma_gemm_kernel<<<dim3(D3_ / 256, (B_ * S_) / 128), 256, GEMM_SMEM_BYTES>>>(
        Aq, Wq, b_qkv, qkv, D3_);

    // 2) attention (HMMA flash) -> split-bf16 g_Ap
    flash_mma_kernel<<<dim3(S_ / 128, H_, B_), 256>>>();

    // 3) output projection (HMMA) -> d_out
    mma_gemm_kernel<<<dim3(D_ / 256, (B_ * S_) / 128), 256, GEMM_SMEM_BYTES>>>(
        Ap, Wp, b_proj, out, D_);
}

// round 16
// speedup vs baseline: 1.0646x; 1.0646x over previous
#include <cuda_runtime.h>
#include <cuda_bf16.h>
#include <math.h>
#include <stdint.h>

// Problem constants
#define B_   8
#define S_   1024
#define D_   1024
#define H_   16
#define HD_  64
#define D3_  3072
#define KP_  3072              // split-bf16 K' = 3*1024
#define LDS_ 40                // smem row stride in bf16 (80B)

// Scratch (device globals; no runtime allocation allowed)
__device__ __align__(128) float         g_qkv[(size_t)B_ * S_ * D3_]; // fp32 QKV
__device__ __align__(128) __nv_bfloat16 g_Aq[(size_t)B_ * S_ * KP_];  // query split
__device__ __align__(128) __nv_bfloat16 g_Ap[(size_t)B_ * S_ * KP_];  // attn-out split
__device__ __align__(128) __nv_bfloat16 g_Wq[(size_t)D3_ * KP_];      // w_qkv'  [N,K']
__device__ __align__(128) __nv_bfloat16 g_Wp[(size_t)D_  * KP_];      // w_proj' [N,K']

__device__ __forceinline__ uint32_t smem_u32(const void* p) {
    uint32_t a;
    asm("{ .reg .u64 t; cvta.to.shared.u64 t, %1; cvt.u32.u64 %0, t; }"
        : "=r"(a) : "l"(p));
    return a;
}

#define LDSM_X4(r0, r1, r2, r3, addr) \
    asm volatile("ldmatrix.sync.aligned.m8n8.x4.shared.b16 {%0,%1,%2,%3}, [%4];" \
                 : "=r"(r0), "=r"(r1), "=r"(r2), "=r"(r3) : "r"(addr))

#define MMA16816(c, a, b) \
    asm volatile("mma.sync.aligned.m16n8k16.row.col.f32.bf16.bf16.f32 " \
                 "{%0,%1,%2,%3}, {%4,%5,%6,%7}, {%8,%9}, {%0,%1,%2,%3};" \
                 : "+f"((c)[0]), "+f"((c)[1]), "+f"((c)[2]), "+f"((c)[3]) \
                 : "r"((a)[0]), "r"((a)[1]), "r"((a)[2]), "r"((a)[3]), \
                   "r"((b)[0]), "r"((b)[1]))

// pack two floats into bf16x2 hi + compensation lo registers
__device__ __forceinline__ void split2(float a, float b, uint32_t& hi, uint32_t& lo) {
    __nv_bfloat16 ha = __float2bfloat16(a), hb = __float2bfloat16(b);
    __nv_bfloat162 th; th.x = ha; th.y = hb;
    __nv_bfloat162 tl;
    tl.x = __float2bfloat16(a - __bfloat162float(ha));
    tl.y = __float2bfloat16(b - __bfloat162float(hb));
    hi = *reinterpret_cast<uint32_t*>(&th);
    lo = *reinterpret_cast<uint32_t*>(&tl);
}

// ---------------------------------------------------------------------------
// Prep: split fp32 activations [rows,1024] -> bf16 [rows,3072] = [hi | lo | hi]
// ---------------------------------------------------------------------------
__global__ __launch_bounds__(256) void conv_A_kernel(const float* __restrict__ in,
                                                     __nv_bfloat16* __restrict__ out) {
    int idx = blockIdx.x * 256 + threadIdx.x;          // one float4 each
    int r = idx >> 8, c4 = (idx & 255) * 4;
    float4 v = *(const float4*)(in + (size_t)r * 1024 + c4);
    float f[4] = {v.x, v.y, v.z, v.w};
    __nv_bfloat16 h[4], l[4];
#pragma unroll
    for (int j = 0; j < 4; j++) {
        h[j] = __float2bfloat16(f[j]);
        l[j] = __float2bfloat16(f[j] - __bfloat162float(h[j]));
    }
    __nv_bfloat16* o = out + (size_t)r * KP_;
    __nv_bfloat162 hp0, hp1, lp0, lp1;
    hp0.x = h[0]; hp0.y = h[1]; hp1.x = h[2]; hp1.y = h[3];
    lp0.x = l[0]; lp0.y = l[1]; lp1.x = l[2]; lp1.y = l[3];
    *(__nv_bfloat162*)(o + c4)        = hp0; *(__nv_bfloat162*)(o + c4 + 2)        = hp1;
    *(__nv_bfloat162*)(o + 1024 + c4) = lp0; *(__nv_bfloat162*)(o + 1024 + c4 + 2) = lp1;
    *(__nv_bfloat162*)(o + 2048 + c4) = hp0; *(__nv_bfloat162*)(o + 2048 + c4 + 2) = hp1;
}

// ---------------------------------------------------------------------------
// Prep: transpose+split weights W[1024,N] fp32 -> W'[N,3072] bf16 = [hi | hi | lo]
// ---------------------------------------------------------------------------
__global__ __launch_bounds__(256) void conv_W_kernel(const float* __restrict__ W,
                                                     __nv_bfloat16* __restrict__ out, int N) {
    __shared__ float t[32][33];
    int n0 = blockIdx.x * 32, k0 = blockIdx.y * 32;
    int tx = threadIdx.x & 31, ty = threadIdx.x >> 5;
#pragma unroll
    for (int i = 0; i < 4; i++)
        t[ty + i * 8][tx] = W[(size_t)(k0 + ty + i * 8) * N + n0 + tx];
    __syncthreads();
    int ny = threadIdx.x >> 3, kq = (threadIdx.x & 7) * 4;
    __nv_bfloat16 h[4], l[4];
#pragma unroll
    for (int j = 0; j < 4; j++) {
        float x = t[kq + j][ny];
        h[j] = __float2bfloat16(x);
        l[j] = __float2bfloat16(x - __bfloat162float(h[j]));
    }
    __nv_bfloat16* o = out + (size_t)(n0 + ny) * KP_ + k0 + kq;
    __nv_bfloat162 hp0, hp1, lp0, lp1;
    hp0.x = h[0]; hp0.y = h[1]; hp1.x = h[2]; hp1.y = h[3];
    lp0.x = l[0]; lp0.y = l[1]; lp1.x = l[2]; lp1.y = l[3];
    *(__nv_bfloat162*)(o)        = hp0; *(__nv_bfloat162*)(o + 2)        = hp1;
    *(__nv_bfloat162*)(o + 1024) = hp0; *(__nv_bfloat162*)(o + 1024 + 2) = hp1;
    *(__nv_bfloat162*)(o + 2048) = lp0; *(__nv_bfloat162*)(o + 2048 + 2) = lp1;
}

// ---------------------------------------------------------------------------
// mma.sync GEMM: C[M,N] = A'[M,K'] @ W'[N,K']^T + bias  (bf16 in, fp32 accum)
// CTA tile 128x128, 4 warps (2x2), warp tile 64x64, BK=32, double-buffered
// 40KB STATIC smem -> 2 CTAs/SM. Combines R13's low L1-traffic-per-MMA
// (8 ldmatrix / 32 MMA) with R12's dual-CTA latency overlap
// (R15 post-mortem: 1 CTA/SM at 60KB smem was latency-bound, issue=15%).
// ---------------------------------------------------------------------------
__global__ __launch_bounds__(128) void mma_gemm_kernel(
    const __nv_bfloat16* __restrict__ A, const __nv_bfloat16* __restrict__ W,
    const float* __restrict__ bias, float* __restrict__ C, int N)
{
    __shared__ __nv_bfloat16 As[2][128 * LDS_];
    __shared__ __nv_bfloat16 Bs[2][128 * LDS_];

    const int tid = threadIdx.x, wid = tid >> 5, lane = tid & 31;
    const int wm = wid >> 1, wn = wid & 1;             // warp grid 2(m) x 2(n)
    const int m0 = blockIdx.y * 128, n0 = blockIdx.x * 128;

    // loaders: 4 threads/row x 8 cols = 32 cols; 32 rows/pass, 4 passes
    const int lr = tid >> 2;                           // 0..31 base row
    const int lc = (tid & 3) * 8;                      // bf16 col offset in BK=32

    float acc[4][8][4];
#pragma unroll
    for (int i = 0; i < 4; i++)
#pragma unroll
        for (int j = 0; j < 8; j++)
#pragma unroll
            for (int k = 0; k < 4; k++) acc[i][j][k] = 0.f;

    // prologue: tile 0 -> buffer 0
#pragma unroll
    for (int i = 0; i < 4; i++) {
        int r = lr + i * 32;
        *(uint4*)&As[0][r * LDS_ + lc] = *(const uint4*)(A + (size_t)(m0 + r) * KP_ + lc);
        *(uint4*)&Bs[0][r * LDS_ + lc] = *(const uint4*)(W + (size_t)(n0 + r) * KP_ + lc);
    }
    __syncthreads();

    const uint32_t a_sm = smem_u32(&As[0][0]);
    const uint32_t b_sm = smem_u32(&Bs[0][0]);
    const uint32_t bufstep = 128 * LDS_ * 2;           // bytes per buffer
    // A-fragment addressing (hardware-validated contract)
    const uint32_t a_row = wm * 64 + (lane & 15);
    const uint32_t a_kof = (lane >> 4) * 8;
    // B-fragment addressing, warp covers 64 n-cols
    const uint32_t b_row = wn * 64 + (lane & 7) + ((lane >> 4) & 1) * 8;
    const uint32_t b_kof = ((lane >> 3) & 1) * 8;

    int buf = 0;
    for (int kt = 0; kt < KP_; kt += 32) {
        const bool more = (kt + 32) < KP_;
        uint4 pa[4], pb[4];
        if (more) {
#pragma unroll
            for (int i = 0; i < 4; i++) {
                pa[i] = *(const uint4*)(A + (size_t)(m0 + lr + i * 32) * KP_ + kt + 32 + lc);
                pb[i] = *(const uint4*)(W + (size_t)(n0 + lr + i * 32) * KP_ + kt + 32 + lc);
            }
        }

        const uint32_t abase = a_sm + buf * bufstep;
        const uint32_t bbase = b_sm + buf * bufstep;
#pragma unroll
        for (int ks = 0; ks < 2; ks++) {               // two k16 sub-steps
            uint32_t a[4][4], b[8][2];
#pragma unroll
            for (int mi = 0; mi < 4; mi++) {
                uint32_t ad = abase + (((a_row + mi * 16) * LDS_) + ks * 16 + a_kof) * 2;
                LDSM_X4(a[mi][0], a[mi][1], a[mi][2], a[mi][3], ad);
            }
#pragma unroll
            for (int nj = 0; nj < 4; nj++) {           // 8 n8-frags via 4 x4 loads
                uint32_t bd = bbase + (((b_row + nj * 16) * LDS_) + ks * 16 + b_kof) * 2;
                LDSM_X4(b[2 * nj][0], b[2 * nj][1], b[2 * nj + 1][0], b[2 * nj + 1][1], bd);
            }
#pragma unroll
            for (int mi = 0; mi < 4; mi++)
#pragma unroll
                for (int ni = 0; ni < 8; ni++)
                    MMA16816(acc[mi][ni], a[mi], b[ni]);
        }

        if (more) {
            const int nb = buf ^ 1;
#pragma unroll
            for (int i = 0; i < 4; i++) {
                *(uint4*)&As[nb][(lr + i * 32) * LDS_ + lc] = pa[i];
                *(uint4*)&Bs[nb][(lr + i * 32) * LDS_ + lc] = pb[i];
            }
        }
        __syncthreads();
        buf ^= 1;
    }

    // epilogue: c frag rows t/4, t/4+8; cols 2*(t%4)+{0,1}
    const int erow = m0 + wm * 64 + (lane >> 2);
    const int ecol = n0 + wn * 64 + (lane & 3) * 2;
#pragma unroll
    for (int mi = 0; mi < 4; mi++) {
#pragma unroll
        for (int ni = 0; ni < 8; ni++) {
            int r0 = erow + mi * 16, c0 = ecol + ni * 8;
            float b0 = bias[c0], b1 = bias[c0 + 1];
            float2 v0 = make_float2(acc[mi][ni][0] + b0, acc[mi][ni][1] + b1);
            float2 v1 = make_float2(acc[mi][ni][2] + b0, acc[mi][ni][3] + b1);
            *(float2*)&C[(size_t)r0 * N + c0]       = v0;
            *(float2*)&C[(size_t)(r0 + 8) * N + c0] = v1;
        }
    }
}

// ---------------------------------------------------------------------------
// Tensor-core flash attention: g_qkv -> g_Ap (split-bf16 [hi|lo|hi] output)
// (byte-identical to the R12-validated kernel)
// ---------------------------------------------------------------------------
__global__ __launch_bounds__(256) void flash_mma_kernel()
{
    __shared__ __align__(16) __nv_bfloat16 sm[18432];   // 36 KB
    const int STR = 72;
    const int QHI = 0, QLO = 9216;
    const int KHI = 0, KLO = 4608, VTHI = 9216, VTLO = 13824;

    const int bz = blockIdx.z, h = blockIdx.y, q0 = blockIdx.x * 128;
    const int tid = threadIdx.x, wid = tid >> 5, lane = tid & 31;
    const float* base = g_qkv + (size_t)bz * S_ * D3_ + h * HD_;

    {
        int qr = tid >> 1, db = (tid & 1) * 32;
        const float* qp = base + (size_t)(q0 + qr) * D3_ + db;
#pragma unroll
        for (int i = 0; i < 8; i++) {
            float4 v = *(const float4*)(qp + i * 4);
            uint32_t hi, lo;
            split2(v.x * 0.125f, v.y * 0.125f, hi, lo);
            *(uint32_t*)&sm[QHI + qr * STR + db + i * 4]     = hi;
            *(uint32_t*)&sm[QLO + qr * STR + db + i * 4]     = lo;
            split2(v.z * 0.125f, v.w * 0.125f, hi, lo);
            *(uint32_t*)&sm[QHI + qr * STR + db + i * 4 + 2] = hi;
            *(uint32_t*)&sm[QLO + qr * STR + db + i * 4 + 2] = lo;
        }
    }
    __syncthreads();

    const uint32_t smb = smem_u32(sm);
    const int arow = wid * 16 + (lane & 15);
    const int akof = (lane >> 4) * 8;
    uint32_t qh[4][4], ql[4][4];
#pragma unroll
    for (int s = 0; s < 4; s++) {
        LDSM_X4(qh[s][0], qh[s][1], qh[s][2], qh[s][3],
                smb + (uint32_t)(QHI + arow * STR + s * 16 + akof) * 2);
        LDSM_X4(ql[s][0], ql[s][1], ql[s][2], ql[s][3],
                smb + (uint32_t)(QLO + arow * STR + s * 16 + akof) * 2);
    }
    __syncthreads();

    float o[8][4];
#pragma unroll
    for (int j = 0; j < 8; j++)
#pragma unroll
        for (int k = 0; k < 4; k++) o[j][k] = 0.f;
    float m0 = -INFINITY, m1 = -INFINITY, l0 = 0.f, l1 = 0.f;

    const int brow = (lane & 7) + ((lane >> 4) & 1) * 8;
    const int bkof = ((lane >> 3) & 1) * 8;

    for (int kt = 0; kt < S_; kt += 64) {
        {
            int key = tid >> 2, db = (tid & 3) * 16;
            const float* kp = base + (size_t)(kt + key) * D3_ + 1024 + db;
#pragma unroll
            for (int i = 0; i < 4; i++) {
                float4 v = *(const float4*)(kp + i * 4);
                uint32_t hi, lo;
                split2(v.x, v.y, hi, lo);
                *(uint32_t*)&sm[KHI + key * STR + db + i * 4]     = hi;
                *(uint32_t*)&sm[KLO + key * STR + db + i * 4]     = lo;
                split2(v.z, v.w, hi, lo);
                *(uint32_t*)&sm[KHI + key * STR + db + i * 4 + 2] = hi;
                *(uint32_t*)&sm[KLO + key * STR + db + i * 4 + 2] = lo;
            }
            const float* vp = base + (size_t)(kt + key) * D3_ + 2048;
            int c = tid & 3;
#pragma unroll
            for (int i = 0; i < 16; i++) {
                int d = c + 4 * i;
                float v = vp[d];
                __nv_bfloat16 hh = __float2bfloat16(v);
                sm[VTHI + d * STR + key] = hh;
                sm[VTLO + d * STR + key] = __float2bfloat16(v - __bfloat162float(hh));
            }
        }
        __syncthreads();

        float sf[8][4];
#pragma unroll
        for (int j = 0; j < 8; j++)
#pragma unroll
            for (int k = 0; k < 4; k++) sf[j][k] = 0.f;
#pragma unroll
        for (int s = 0; s < 4; s++) {
            uint32_t bh[8][2], bl[8][2];
#pragma unroll
            for (int nj = 0; nj < 4; nj++) {
                uint32_t ad = smb + (uint32_t)(KHI + (brow + 16 * nj) * STR + s * 16 + bkof) * 2;
                LDSM_X4(bh[2 * nj][0], bh[2 * nj][1], bh[2 * nj + 1][0], bh[2 * nj + 1][1], ad);
                uint32_t al = smb + (uint32_t)(KLO + (brow + 16 * nj) * STR + s * 16 + bkof) * 2;
                LDSM_X4(bl[2 * nj][0], bl[2 * nj][1], bl[2 * nj + 1][0], bl[2 * nj + 1][1], al);
            }
#pragma unroll
            for (int j = 0; j < 8; j++) {
                MMA16816(sf[j], qh[s], bh[j]);
                MMA16816(sf[j], ql[s], bh[j]);
                MMA16816(sf[j], qh[s], bl[j]);
            }
        }

        float mx0 = -INFINITY, mx1 = -INFINITY;
#pragma unroll
        for (int j = 0; j < 8; j++) {
            mx0 = fmaxf(mx0, fmaxf(sf[j][0], sf[j][1]));
            mx1 = fmaxf(mx1, fmaxf(sf[j][2], sf[j][3]));
        }
#pragma unroll
        for (int off = 1; off <= 2; off <<= 1) {
            mx0 = fmaxf(mx0, __shfl_xor_sync(0xffffffffu, mx0, off));
            mx1 = fmaxf(mx1, __shfl_xor_sync(0xffffffffu, mx1, off));
        }
        float mn0 = fmaxf(m0, mx0), mn1 = fmaxf(m1, mx1);
        float f0 = __expf(m0 - mn0), f1 = __expf(m1 - mn1);
        m0 = mn0; m1 = mn1;

        float rs0 = 0.f, rs1 = 0.f;
        uint32_t pH0[8], pH1[8], pL0[8], pL1[8];
#pragma unroll
        for (int j = 0; j < 8; j++) {
            float p0 = __expf(sf[j][0] - mn0), p1 = __expf(sf[j][1] - mn0);
            float p2 = __expf(sf[j][2] - mn1), p3 = __expf(sf[j][3] - mn1);
            rs0 += p0 + p1; rs1 += p2 + p3;
            split2(p0, p1, pH0[j], pL0[j]);
            split2(p2, p3, pH1[j], pL1[j]);
        }
#pragma unroll
        for (int off = 1; off <= 2; off <<= 1) {
            rs0 += __shfl_xor_sync(0xffffffffu, rs0, off);
            rs1 += __shfl_xor_sync(0xffffffffu, rs1, off);
        }
        l0 = l0 * f0 + rs0;
        l1 = l1 * f1 + rs1;
#pragma unroll
        for (int j = 0; j < 8; j++) {
            o[j][0] *= f0; o[j][1] *= f0; o[j][2] *= f1; o[j][3] *= f1;
        }

#pragma unroll
        for (int t = 0; t < 4; t++) {
            uint32_t vh[8][2], vl[8][2];
#pragma unroll
            for (int nj = 0; nj < 4; nj++) {
                uint32_t ad = smb + (uint32_t)(VTHI + (brow + 16 * nj) * STR + t * 16 + bkof) * 2;
                LDSM_X4(vh[2 * nj][0], vh[2 * nj][1], vh[2 * nj + 1][0], vh[2 * nj + 1][1], ad);
                uint32_t al = smb + (uint32_t)(VTLO + (brow + 16 * nj) * STR + t * 16 + bkof) * 2;
                LDSM_X4(vl[2 * nj][0], vl[2 * nj][1], vl[2 * nj + 1][0], vl[2 * nj + 1][1], al);
            }
            uint32_t aH[4] = {pH0[2 * t], pH1[2 * t], pH0[2 * t + 1], pH1[2 * t + 1]};
            uint32_t aL[4] = {pL0[2 * t], pL1[2 * t], pL0[2 * t + 1], pL1[2 * t + 1]};
#pragma unroll
            for (int jd = 0; jd < 8; jd++) {
                MMA16816(o[jd], aH, vh[jd]);
                MMA16816(o[jd], aL, vh[jd]);
                MMA16816(o[jd], aH, vl[jd]);
            }
        }
        __syncthreads();
    }

    const float inv0 = 1.f / l0, inv1 = 1.f / l1;
    const size_t row0 = (size_t)bz * S_ + q0 + wid * 16 + (lane >> 2);
    __nv_bfloat16* op0 = g_Ap + row0 * KP_ + h * HD_ + 2 * (lane & 3);
    __nv_bfloat16* op1 = op0 + (size_t)8 * KP_;
#pragma unroll
    for (int jd = 0; jd < 8; jd++) {
        uint32_t hi, lo;
        split2(o[jd][0] * inv0, o[jd][1] * inv0, hi, lo);
        *(uint32_t*)(op0 + 8 * jd)        = hi;
        *(uint32_t*)(op0 + 8 * jd + 1024) = lo;
        *(uint32_t*)(op0 + 8 * jd + 2048) = hi;
        split2(o[jd][2] * inv1, o[jd][3] * inv1, hi, lo);
        *(uint32_t*)(op1 + 8 * jd)        = hi;
        *(uint32_t*)(op1 + 8 * jd + 1024) = lo;
        *(uint32_t*)(op1 + 8 * jd + 2048) = hi;
    }
}

// ---------------------------------------------------------------------------
extern "C" void kernel_launch(void* const* d_in, const int* in_sizes, int n_in,
                              void* d_out, int out_size)
{
    const float* query  = (const float*)d_in[0];
    const float* w_qkv  = (const float*)d_in[1];
    const float* b_qkv  = (const float*)d_in[2];
    const float* w_proj = (const float*)d_in[3];
    const float* b_proj = (const float*)d_in[4];
    float* out = (float*)d_out;

    float* qkv = nullptr;
    __nv_bfloat16 *Aq = nullptr, *Ap = nullptr, *Wq = nullptr, *Wp = nullptr;
    cudaGetSymbolAddress((void**)&qkv, g_qkv);
    cudaGetSymbolAddress((void**)&Aq, g_Aq);
    cudaGetSymbolAddress((void**)&Ap, g_Ap);
    cudaGetSymbolAddress((void**)&Wq, g_Wq);
    cudaGetSymbolAddress((void**)&Wp, g_Wp);

    // prep: split/transpose
    conv_A_kernel<<<(B_ * S_ * 1024) / (256 * 4), 256>>>(query, Aq);
    conv_W_kernel<<<dim3(D3_ / 32, 32), 256>>>(w_qkv, Wq, D3_);
    conv_W_kernel<<<dim3(D_ / 32, 32), 256>>>(w_proj, Wp, D_);

    // 1) QKV projection (HMMA): [8192,3072'] @ [3072,3072']^T -> fp32 g_qkv
    mma_gemm_kernel<<<dim3(D3_ / 128, (B_ * S_) / 128), 128>>>(
        Aq, Wq, b_qkv, qkv, D3_);

    // 2) attention (HMMA flash) -> split-bf16 g_Ap
    flash_mma_kernel<<<dim3(S_ / 128, H_, B_), 256>>>();

    // 3) output projection (HMMA) -> d_out
    mma_gemm_kernel<<<dim3(D_ / 128, (B_ * S_) / 128), 128>>>(
        Ap, Wp, b_proj, out, D_);
}